// round 15
// baseline (speedup 1.0000x reference)
#include <cuda_runtime.h>
#include <cuda_fp16.h>
#include <math.h>
#include <cstdint>

typedef unsigned long long ull;

// Problem dims
#define S_   4096
#define T_   64
#define I_   64
#define EH_  128
#define E_   256
#define H_   512
#define O_   128
#define F1_  256
#define F2_  64
#define G4H_ (4*H_)       // 2048
#define KG_  (E_+H_)      // 768
#define NK16W (KG_/16)    // 48
#define NN16 (G4H_/16)    // 128
#define ST_  (S_*T_)      // 262144

// ---------------- device scratch ----------------
__device__ float g_laneC;
__device__ __half g_x1h[(size_t)ST_ * EH_];      // x1 fp16 hi
__device__ __half g_x1l[(size_t)ST_ * EH_];      // x1 fp16 lo
__device__ __half g_xemb_hi[(size_t)ST_ * E_];   // [T][S][E]
__device__ __half g_xemb_lo[(size_t)ST_ * E_];
__device__ uint4 g_Bfrag[(size_t)NK16W * NN16 * 32];   // 3.1 MB gates W fragments
__device__ uint4 g_W2frag[(size_t)16 * 16 * 32];       // 128 KB We2 fragments (hi 0-7, lo 8-15)
__device__ float g_bcomb[G4H_];
__device__ float g_h[(size_t)S_ * H_];
__device__ __half g_hhi[(size_t)S_ * H_];
__device__ __half g_hlo[(size_t)S_ * H_];
__device__ float g_hraw[(size_t)S_ * H_];
__device__ float g_c[(size_t)S_ * H_];
__device__ float g_o1[(size_t)S_ * O_];
__device__ float g_o2[(size_t)S_ * F1_];
__device__ float g_o3[(size_t)S_ * F2_];

// ---------------- helpers ----------------
__device__ __forceinline__ uint32_t smem_u32(const void* p) {
    uint32_t a;
    asm("{ .reg .u64 t; cvta.to.shared.u64 t, %1; cvt.u32.u64 %0, t; }" : "=r"(a) : "l"(p));
    return a;
}
#define CP16(dst, src) asm volatile("cp.async.cg.shared.global [%0], [%1], 16;" :: "r"(dst), "l"(src))
#define CP_COMMIT()    asm volatile("cp.async.commit_group;" ::: "memory")
#define CP_WAIT1()     asm volatile("cp.async.wait_group 1;" ::: "memory")
#define CP_WAIT0()     asm volatile("cp.async.wait_group 0;" ::: "memory")

#define MMA16816(c, a, b) \
    asm volatile("mma.sync.aligned.m16n8k16.row.col.f32.f16.f16.f32 " \
        "{%0,%1,%2,%3}, {%4,%5,%6,%7}, {%8,%9}, {%0,%1,%2,%3};" \
        : "+f"((c)[0]), "+f"((c)[1]), "+f"((c)[2]), "+f"((c)[3]) \
        : "r"((a)[0]), "r"((a)[1]), "r"((a)[2]), "r"((a)[3]), \
          "r"((b)[0]), "r"((b)[1]))

#define LDSM4(r0, r1, r2, r3, addr) \
    asm volatile("ldmatrix.sync.aligned.m8n8.x4.shared.b16 {%0,%1,%2,%3}, [%4];" \
        : "=r"(r0), "=r"(r1), "=r"(r2), "=r"(r3) : "r"(addr))

#define FMA2(d, a, b) asm("fma.rn.f32x2 %0, %1, %2, %0;" : "+l"(d) : "l"(a), "l"(b))
#define PACK2(d, x)   asm("mov.b64 %0, {%1, %1};" : "=l"(d) : "f"(x))
__device__ __forceinline__ float2 unpk(ull v) {
    float2 r;
    asm("mov.b64 {%0, %1}, %2;" : "=f"(r.x), "=f"(r.y) : "l"(v));
    return r;
}
__device__ __forceinline__ float sigf(float x) { return __fdividef(1.0f, 1.0f + __expf(-x)); }
__device__ __forceinline__ float tanhf_(float x) {
    return 2.0f * __fdividef(1.0f, 1.0f + __expf(-2.0f * x)) - 1.0f;
}
__device__ __forceinline__ uint32_t pack_h2(__half a, __half b) {
    uint16_t ua = *reinterpret_cast<uint16_t*>(&a);
    uint16_t ub = *reinterpret_cast<uint16_t*>(&b);
    return (uint32_t)ua | ((uint32_t)ub << 16);
}

// ---------------- prep: gates W fragments + We2 fragments + bias + lane gate ----------------
__global__ void prep_all(const float* __restrict__ Wih, const float* __restrict__ Whh,
                         const float* __restrict__ bih, const float* __restrict__ bhh,
                         const float* __restrict__ We2,
                         const float* __restrict__ lane,
                         const float* __restrict__ Wlg1, const float* __restrict__ blg1,
                         const float* __restrict__ Wlg2, const float* __restrict__ blg2) {
    int k16 = blockIdx.x;   // 0..47
    int n16 = blockIdx.y;   // 0..127
    int ln = threadIdx.x;   // 0..31

    // gates weights (fp16 single)
    {
        uint32_t vals[4];
#pragma unroll
        for (int j = 0; j < 4; j++) {
            int n = n16 * 16 + ((j >> 1) * 8) + (ln >> 2);
            int kp = k16 * 16 + ((j & 1) * 8) + (ln & 3) * 2;
            int orig = (n & 3) * H_ + (n >> 2);
            float w0 = (kp < E_) ? Wih[(size_t)orig * E_ + kp] : Whh[(size_t)orig * H_ + (kp - E_)];
            int kp1 = kp + 1;
            float w1 = (kp1 < E_) ? Wih[(size_t)orig * E_ + kp1] : Whh[(size_t)orig * H_ + (kp1 - E_)];
            vals[j] = pack_h2(__float2half(w0), __float2half(w1));
        }
        g_Bfrag[((size_t)k16 * NN16 + n16) * 32 + ln] =
            make_uint4(vals[0], vals[1], vals[2], vals[3]);
    }

    // We2 fragments: k16 slots 0-7 = hi, 8-15 = lo  (We2 is [E,EH] = [256,128])
    if (k16 < 16 && n16 < 16) {
        uint32_t vals[4];
#pragma unroll
        for (int j = 0; j < 4; j++) {
            int n = n16 * 16 + ((j >> 1) * 8) + (ln >> 2);    // 0..255
            int kp = (k16 & 7) * 16 + ((j & 1) * 8) + (ln & 3) * 2;  // 0..127
            float w0 = We2[(size_t)n * EH_ + kp];
            float w1 = We2[(size_t)n * EH_ + kp + 1];
            __half h0, h1;
            if (k16 < 8) { h0 = __float2half(w0); h1 = __float2half(w1); }
            else {
                __half a = __float2half(w0), b = __float2half(w1);
                h0 = __float2half(w0 - __half2float(a));
                h1 = __float2half(w1 - __half2float(b));
            }
            vals[j] = pack_h2(h0, h1);
        }
        g_W2frag[((size_t)k16 * 16 + n16) * 32 + ln] =
            make_uint4(vals[0], vals[1], vals[2], vals[3]);
    }

    if (k16 == 0 && ln < 16) {
        int r = n16 * 16 + ln;
        int orig = (r & 3) * H_ + (r >> 2);
        g_bcomb[r] = bih[orig] + bhh[orig];
    }
    if (k16 == 0 && n16 == 0) {
        float lg = fmaxf(lane[0] * Wlg1[ln] + blg1[ln], 0.0f);
        float p = lg * Wlg2[ln];
#pragma unroll
        for (int o = 16; o > 0; o >>= 1) p += __shfl_down_sync(0xFFFFFFFFu, p, o);
        if (ln == 0) g_laneC = 1.0f / (1.0f + expf(-(p + blg2[0])));
    }
}

// ---------------- scalar FFMA2 SGEMM (embedding GEMM1 + head) ----------------
#define BM 128
#define BN 128
#define BK 8
#define FL_RELU    1
#define FL_SCALEA  2
#define FL_SPLIT1  8   // write fp16 hi/lo to g_x1h/g_x1l (row-major)

__global__ __launch_bounds__(256, 2)
void sgemm2(int M, int N, int K,
            const float* __restrict__ A, int lda,
            const float* __restrict__ B,
            const float* __restrict__ bias,
            float* __restrict__ C, int ldc, int flags)
{
    __shared__ __align__(16) float As[BK][BM];
    __shared__ __align__(16) float Bs[BK][BN];

    const int tid = threadIdx.x;
    const int tx = tid & 15;
    const int ty = tid >> 4;
    const int bm = blockIdx.y * BM;
    const int bn = blockIdx.x * BN;
    const float scale = (flags & FL_SCALEA) ? g_laneC : 1.0f;
    const int lRow = tid >> 1;
    const int lCol = (tid & 1) * 4;

    ull acc[8][4];
#pragma unroll
    for (int i = 0; i < 8; i++)
#pragma unroll
        for (int p = 0; p < 4; p++) acc[i][p] = 0ull;

    for (int k0 = 0; k0 < K; k0 += BK) {
        float4 av = make_float4(0.f, 0.f, 0.f, 0.f);
        int ar = bm + lRow;
        if (ar < M) av = *reinterpret_cast<const float4*>(A + (size_t)ar * lda + (k0 + lCol));
        As[lCol + 0][lRow] = av.x * scale;
        As[lCol + 1][lRow] = av.y * scale;
        As[lCol + 2][lRow] = av.z * scale;
        As[lCol + 3][lRow] = av.w * scale;

        float4 bv = make_float4(0.f, 0.f, 0.f, 0.f);
        int br = bn + lRow;
        if (br < N) bv = *reinterpret_cast<const float4*>(B + (size_t)br * K + (k0 + lCol));
        Bs[lCol + 0][lRow] = bv.x;
        Bs[lCol + 1][lRow] = bv.y;
        Bs[lCol + 2][lRow] = bv.z;
        Bs[lCol + 3][lRow] = bv.w;

        __syncthreads();
#pragma unroll
        for (int k = 0; k < BK; k++) {
            float4 a0 = *reinterpret_cast<const float4*>(&As[k][ty * 4]);
            float4 a1 = *reinterpret_cast<const float4*>(&As[k][64 + ty * 4]);
            const ull* bp0 = reinterpret_cast<const ull*>(&Bs[k][tx * 4]);
            const ull* bp1 = reinterpret_cast<const ull*>(&Bs[k][64 + tx * 4]);
            ull b0 = bp0[0], b1 = bp0[1], b2 = bp1[0], b3 = bp1[1];
            float as[8] = {a0.x, a0.y, a0.z, a0.w, a1.x, a1.y, a1.z, a1.w};
            ull aa;
#pragma unroll
            for (int i = 0; i < 8; i++) {
                PACK2(aa, as[i]);
                FMA2(acc[i][0], aa, b0);
                FMA2(acc[i][1], aa, b1);
                FMA2(acc[i][2], aa, b2);
                FMA2(acc[i][3], aa, b3);
            }
        }
        __syncthreads();
    }

#pragma unroll
    for (int i = 0; i < 8; i++) {
        int row = bm + ((i < 4) ? (ty * 4 + i) : (64 + ty * 4 + (i - 4)));
        if (row >= M) continue;
#pragma unroll
        for (int p = 0; p < 4; p++) {
            float2 v = unpk(acc[i][p]);
            int c0 = bn + ((p < 2) ? (tx * 4 + p * 2) : (64 + tx * 4 + (p - 2) * 2));
#pragma unroll
            for (int q = 0; q < 2; q++) {
                int col = c0 + q;
                if (col >= N) continue;
                float val = (q == 0) ? v.x : v.y;
                if (bias) val += bias[col];
                if (flags & FL_RELU) val = fmaxf(val, 0.0f);
                if (flags & FL_SPLIT1) {
                    __half hi = __float2half(val);
                    g_x1h[(size_t)row * EH_ + col] = hi;
                    g_x1l[(size_t)row * EH_ + col] = __float2half(val - __half2float(hi));
                } else {
                    C[(size_t)row * ldc + col] = val;
                }
            }
        }
    }
}

// ---------------- shared mma-mainloop constants ----------------
#define GBK 128
#define AROW 272                   // 256 B row + 16 pad
#define A_BYTES (128 * AROW)       // 34816 per stage
#define SM_TOT  (2 * A_BYTES)      // 69632

// ============ embedding GEMM2 on tensor cores: xemb = relu(x1 @ We2^T + be2) ============
// 3-term fp16 split over K'=384 (3 chunks): x_hi*W_hi + x_lo*W_hi + x_hi*W_lo.
// Epilogue: bias+relu, fp16 hi/lo split, [T][S][E] permuted store.
__global__ __launch_bounds__(256, 2)
void emb_mma(const float* __restrict__ be2)
{
    extern __shared__ char smem[];
    const uint32_t sb = smem_u32(smem);
    const int tid = threadIdx.x;
    const int lane = tid & 31;
    const int wid = tid >> 5;
    const int wm = wid & 3;        // 4 row-warps (32 rows)
    const int wn = wid >> 2;       // 2 col-warps (64 cols)
    const int bm = blockIdx.y * 128;
    const int bn = blockIdx.x * 128;
    const int n16b = blockIdx.x * 8 + wn * 4;   // 0..15

    float acc[2][8][4];
#pragma unroll
    for (int mf = 0; mf < 2; mf++)
#pragma unroll
        for (int nf = 0; nf < 8; nf++)
#pragma unroll
            for (int r = 0; r < 4; r++) acc[mf][nf][r] = 0.0f;

    auto load_chunk = [&](int ck, int st) {
        const __half* asrc = ((ck == 1) ? g_x1l : g_x1h) + (size_t)bm * EH_;
        const uint32_t abase = sb + (uint32_t)(st * A_BYTES);
#pragma unroll
        for (int it = 0; it < 8; it++) {
            int i = tid + it * 256;
            int row = i >> 4, sg = i & 15;
            CP16(abase + row * AROW + sg * 16, asrc + (size_t)row * EH_ + sg * 8);
        }
    };

    const int grp = lane >> 3, lr = lane & 7;
    const int a_row = wm * 32 + (grp & 1) * 8 + lr;
    const int a_kh  = (grp >> 1) * 8;
    const uint4* __restrict__ bfp = g_W2frag + lane;

    load_chunk(0, 0);
    CP_COMMIT();

    const int k16bases[3] = {0, 0, 8};   // W hi, hi, lo
#pragma unroll
    for (int ck = 0; ck < 3; ck++) {
        const int st = ck & 1;
        if (ck + 1 < 3) {
            load_chunk(ck + 1, st ^ 1);
            CP_COMMIT();
            CP_WAIT1();
        } else {
            CP_WAIT0();
        }
        __syncthreads();

        const uint32_t abase = sb + (uint32_t)(st * A_BYTES);
        const int k16base = k16bases[ck];

        uint4 bv[4];
#pragma unroll
        for (int q = 0; q < 4; q++)
            bv[q] = __ldg(bfp + ((size_t)k16base * 16 + (n16b + q)) * 32);

#pragma unroll
        for (int kh = 0; kh < 8; kh++) {
            uint4 bnx[4];
            if (kh < 7) {
#pragma unroll
                for (int q = 0; q < 4; q++)
                    bnx[q] = __ldg(bfp + ((size_t)(k16base + kh + 1) * 16 + (n16b + q)) * 32);
            }
            const int k0 = kh * 16;
            uint32_t af[2][4];
#pragma unroll
            for (int mf = 0; mf < 2; mf++)
                LDSM4(af[mf][0], af[mf][1], af[mf][2], af[mf][3],
                      abase + (uint32_t)((a_row + mf * 16) * AROW + (k0 + a_kh) * 2));
            uint32_t bf[8][2];
#pragma unroll
            for (int q = 0; q < 4; q++) {
                bf[2 * q][0] = bv[q].x;
                bf[2 * q][1] = bv[q].y;
                bf[2 * q + 1][0] = bv[q].z;
                bf[2 * q + 1][1] = bv[q].w;
            }
#pragma unroll
            for (int mf = 0; mf < 2; mf++)
#pragma unroll
                for (int nf = 0; nf < 8; nf++)
                    MMA16816(acc[mf][nf], af[mf], bf[nf]);
#pragma unroll
            for (int q = 0; q < 4; q++) bv[q] = bnx[q];
        }
        __syncthreads();
    }

    // ---- epilogue: bias + relu + fp16 split + [T][S][E] permuted store ----
    const int qg = lane & 3;
#pragma unroll
    for (int mf = 0; mf < 2; mf++) {
        const int r0 = bm + wm * 32 + mf * 16 + (lane >> 2);
        const size_t orow0 = ((size_t)(r0 & (T_ - 1)) * S_ + (r0 >> 6));
        const size_t orow1 = ((size_t)((r0 + 8) & (T_ - 1)) * S_ + ((r0 + 8) >> 6));
#pragma unroll
        for (int nf = 0; nf < 8; nf++) {
            const int c = bn + wn * 64 + nf * 8 + qg * 2;
            float2 bb = *reinterpret_cast<const float2*>(&be2[c]);
#pragma unroll
            for (int h = 0; h < 2; h++) {
                float v0 = fmaxf(acc[mf][nf][h * 2 + 0] + bb.x, 0.0f);
                float v1 = fmaxf(acc[mf][nf][h * 2 + 1] + bb.y, 0.0f);
                __half h0 = __float2half(v0);
                __half h1 = __float2half(v1);
                __half l0 = __float2half(v0 - __half2float(h0));
                __half l1 = __float2half(v1 - __half2float(h1));
                size_t orow = h ? orow1 : orow0;
                *reinterpret_cast<uint32_t*>(&g_xemb_hi[orow * E_ + c]) = pack_h2(h0, h1);
                *reinterpret_cast<uint32_t*>(&g_xemb_lo[orow * E_ + c]) = pack_h2(l0, l1);
            }
        }
    }
}

// ============ gates GEMM (fp16 2-term, GBK=128) — R14 structure unchanged ============
__global__ __launch_bounds__(256, 2)
void gates_mma(int t)
{
    extern __shared__ char smem[];
    const uint32_t sb = smem_u32(smem);
    const int tid = threadIdx.x;
    const int lane = tid & 31;
    const int wid = tid >> 5;
    const int wm = wid & 3;
    const int wn = wid >> 2;
    const int bm = blockIdx.y * 128;
    const int bn = blockIdx.x * 128;
    const int n16b = blockIdx.x * 8 + wn * 4;

    const int nch = (t == 0) ? 4 : 12;
    const int per = (t == 0) ? 2 : 6;

    float acc[2][8][4];
#pragma unroll
    for (int mf = 0; mf < 2; mf++)
#pragma unroll
        for (int nf = 0; nf < 8; nf++)
#pragma unroll
            for (int r = 0; r < 4; r++) acc[mf][nf][r] = 0.0f;

    auto load_chunk = [&](int ck, int st) {
        const int seg = ck / per;
        const int kk = (ck % per) * GBK;
        const __half* asrc;
        size_t astr;
        if (kk < E_) {
            asrc = ((seg == 1) ? g_xemb_lo : g_xemb_hi) + ((size_t)t * S_ + bm) * E_ + kk;
            astr = E_;
        } else {
            asrc = ((seg == 1) ? g_hlo : g_hhi) + (size_t)bm * H_ + (kk - E_);
            astr = H_;
        }
        const uint32_t abase = sb + (uint32_t)(st * A_BYTES);
#pragma unroll
        for (int it = 0; it < 8; it++) {
            int i = tid + it * 256;
            int row = i >> 4, sg = i & 15;
            CP16(abase + row * AROW + sg * 16, asrc + (size_t)row * astr + sg * 8);
        }
    };
    auto k16_of = [&](int ck) { return (ck % per) * 8; };

    const int grp = lane >> 3, lr = lane & 7;
    const int a_row = wm * 32 + (grp & 1) * 8 + lr;
    const int a_kh  = (grp >> 1) * 8;
    const uint4* __restrict__ bfp = g_Bfrag + lane;

    load_chunk(0, 0);
    CP_COMMIT();

    for (int ck = 0; ck < nch; ck++) {
        const int st = ck & 1;
        if (ck + 1 < nch) {
            load_chunk(ck + 1, st ^ 1);
            CP_COMMIT();
            CP_WAIT1();
        } else {
            CP_WAIT0();
        }
        __syncthreads();

        const uint32_t abase = sb + (uint32_t)(st * A_BYTES);
        const int k16base = k16_of(ck);

        uint4 bv[4];
#pragma unroll
        for (int q = 0; q < 4; q++)
            bv[q] = __ldg(bfp + ((size_t)k16base * NN16 + (n16b + q)) * 32);

#pragma unroll
        for (int kh = 0; kh < 8; kh++) {
            uint4 bnx[4];
            if (kh < 7) {
#pragma unroll
                for (int q = 0; q < 4; q++)
                    bnx[q] = __ldg(bfp + ((size_t)(k16base + kh + 1) * NN16 + (n16b + q)) * 32);
            }
            const int k0 = kh * 16;
            uint32_t af[2][4];
#pragma unroll
            for (int mf = 0; mf < 2; mf++)
                LDSM4(af[mf][0], af[mf][1], af[mf][2], af[mf][3],
                      abase + (uint32_t)((a_row + mf * 16) * AROW + (k0 + a_kh) * 2));
            uint32_t bf[8][2];
#pragma unroll
            for (int q = 0; q < 4; q++) {
                bf[2 * q][0] = bv[q].x;
                bf[2 * q][1] = bv[q].y;
                bf[2 * q + 1][0] = bv[q].z;
                bf[2 * q + 1][1] = bv[q].w;
            }
#pragma unroll
            for (int mf = 0; mf < 2; mf++)
#pragma unroll
                for (int nf = 0; nf < 8; nf++)
                    MMA16816(acc[mf][nf], af[mf], bf[nf]);
#pragma unroll
            for (int q = 0; q < 4; q++) bv[q] = bnx[q];
        }
        __syncthreads();
    }

    // ---- register epilogue: shfl pairs (i,f)<->(g,o), fused LSTM cell ----
    const int qg = lane & 3;
    const bool evenT = (qg & 1) == 0;
    const int unit_base = (bn + wn * 64) >> 2;
#pragma unroll
    for (int mf = 0; mf < 2; mf++) {
        const int rloc = wm * 32 + mf * 16 + (lane >> 2);
#pragma unroll
        for (int nf = 0; nf < 8; nf++) {
            const int col0 = bn + wn * 64 + nf * 8 + qg * 2;
            float2 bb = *reinterpret_cast<const float2*>(&g_bcomb[col0]);
            float c0 = acc[mf][nf][0] + bb.x;
            float c1 = acc[mf][nf][1] + bb.y;
            float c2 = acc[mf][nf][2] + bb.x;
            float c3 = acc[mf][nf][3] + bb.y;
            float x0 = __shfl_xor_sync(0xFFFFFFFFu, c0, 1);
            float x1 = __shfl_xor_sync(0xFFFFFFFFu, c1, 1);
            float x2 = __shfl_xor_sync(0xFFFFFFFFu, c2, 1);
            float x3 = __shfl_xor_sync(0xFFFFFFFFu, c3, 1);
            float iv, fv, gv, ov; int rr;
            if (evenT) { iv = c0; fv = c1; gv = x0; ov = x1; rr = rloc; }
            else       { iv = x2; fv = x3; gv = c2; ov = c3; rr = rloc + 8; }
            const int unit = unit_base + nf * 2 + (qg >> 1);
            size_t cidx = (size_t)(bm + rr) * H_ + unit;
            float cold = (t == 0) ? 0.0f : g_c[cidx];
            float cn = sigf(fv) * cold + sigf(iv) * tanhf_(gv);
            g_c[cidx] = cn;
            g_hraw[cidx] = sigf(ov) * tanhf_(cn);
        }
    }
}

// ---------------- spatial maxpool + fp16 split of h ----------------
__global__ void maxpool_kernel(int writeH) {
    int idx = blockIdx.x * blockDim.x + threadIdx.x;
    if (idx >= S_ * H_) return;
    int s = idx >> 9;
    float v = g_hraw[idx];
    if (s > 0)       v = fmaxf(v, g_hraw[idx - H_]);
    if (s < S_ - 1)  v = fmaxf(v, g_hraw[idx + H_]);
    if (writeH) g_h[idx] = v;
    __half hi = __float2half(v);
    g_hhi[idx] = hi;
    g_hlo[idx] = __float2half(v - __half2float(hi));
}

// ---------------- final head ----------------
__global__ void head_final_kernel(const float* __restrict__ Wf3,
                                  const float* __restrict__ bf3,
                                  float* __restrict__ out) {
    __shared__ float red[F2_];
    int s = blockIdx.x;
    int t = threadIdx.x;
    red[t] = g_o3[(size_t)s * F2_ + t] * Wf3[t];
    __syncthreads();
#pragma unroll
    for (int o = 32; o > 0; o >>= 1) {
        if (t < o) red[t] += red[t + o];
        __syncthreads();
    }
    if (t == 0) out[s] = (red[0] + bf3[0]) / g_laneC;
}

__global__ void finalize_kernel(float* __restrict__ out) {
    int idx = blockIdx.x * blockDim.x + threadIdx.x;
    if (idx >= S_ * H_) return;
    out[S_ + idx] = g_h[idx];
    out[S_ + (size_t)S_ * H_ + idx] = g_c[idx];
}

// ---------------- host launcher ----------------
extern "C" void kernel_launch(void* const* d_in, const int* in_sizes, int n_in,
                              void* d_out, int out_size) {
    const float* inputData = (const float*)d_in[0];
    const float* lane      = (const float*)d_in[1];
    const float* Wlg1      = (const float*)d_in[2];
    const float* blg1      = (const float*)d_in[3];
    const float* Wlg2      = (const float*)d_in[4];
    const float* blg2      = (const float*)d_in[5];
    const float* We1       = (const float*)d_in[6];
    const float* be1       = (const float*)d_in[7];
    const float* We2       = (const float*)d_in[8];
    const float* be2       = (const float*)d_in[9];
    const float* Wih       = (const float*)d_in[10];
    const float* bih       = (const float*)d_in[11];
    const float* Whh       = (const float*)d_in[12];
    const float* bhh       = (const float*)d_in[13];
    const float* Wout      = (const float*)d_in[14];
    const float* bout      = (const float*)d_in[15];
    const float* Wf1       = (const float*)d_in[16];
    const float* bf1       = (const float*)d_in[17];
    const float* Wf2       = (const float*)d_in[18];
    const float* bf2       = (const float*)d_in[19];
    const float* Wf3       = (const float*)d_in[20];
    const float* bf3       = (const float*)d_in[21];
    float* out = (float*)d_out;

    float *p_h, *p_o1, *p_o2, *p_o3;
    cudaGetSymbolAddress((void**)&p_h,  g_h);
    cudaGetSymbolAddress((void**)&p_o1, g_o1);
    cudaGetSymbolAddress((void**)&p_o2, g_o2);
    cudaGetSymbolAddress((void**)&p_o3, g_o3);

    static int smem_set = 0;
    if (!smem_set) {
        cudaFuncSetAttribute(gates_mma, cudaFuncAttributeMaxDynamicSharedMemorySize, SM_TOT);
        cudaFuncSetAttribute(emb_mma, cudaFuncAttributeMaxDynamicSharedMemorySize, SM_TOT);
        smem_set = 1;
    }

    dim3 blk(256);

    // #1: prep (gates W frags + We2 frags + bias + lane gate)
    prep_all<<<dim3(NK16W, NN16), 32>>>(Wih, Whh, bih, bhh, We2,
                                        lane, Wlg1, blg1, Wlg2, blg2);
    // #2: embedding GEMM1 (scalar; writes x1 fp16 hi/lo)
    sgemm2<<<dim3(EH_ / BN, ST_ / BM), blk>>>(ST_, EH_, I_, inputData, I_, We1, be1,
                                              nullptr, EH_, FL_RELU | FL_SCALEA | FL_SPLIT1);
    // #3: embedding GEMM2 on tensor cores (writes xemb hi/lo permuted)
    emb_mma<<<dim3(E_ / 128, ST_ / 128), blk, SM_TOT>>>(be2);

    // #4 onward: recurrence (gates t=0 is the profiled launch)
    int ew = S_ * H_;
    dim3 ggrid(G4H_ / 128, S_ / 128);  // 16 x 32 = 512 CTAs
    for (int t = 0; t < T_; t++) {
        gates_mma<<<ggrid, 256, SM_TOT>>>(t);
        maxpool_kernel<<<(ew + 255) / 256, 256>>>(t == T_ - 1 ? 1 : 0);
    }

    // output head (scalar GEMMs; small)
    sgemm2<<<dim3(O_ / BN, S_ / BM), blk>>>(S_, O_, H_, p_h, H_, Wout, bout,
                                            p_o1, O_, 0);
    sgemm2<<<dim3((F1_ + BN - 1) / BN, S_ / BM), blk>>>(S_, F1_, O_, p_o1, O_, Wf1, bf1,
                                                        p_o2, F1_, FL_RELU);
    sgemm2<<<dim3((F2_ + BN - 1) / BN, S_ / BM), blk>>>(S_, F2_, F1_, p_o2, F1_, Wf2, bf2,
                                                        p_o3, F2_, FL_RELU);
    head_final_kernel<<<S_, F2_>>>(Wf3, bf3, out);
    finalize_kernel<<<(ew + 255) / 256, 256>>>(out);
}

// round 16
// speedup vs baseline: 1.3265x; 1.3265x over previous
#include <cuda_runtime.h>
#include <cuda_fp16.h>
#include <math.h>
#include <cstdint>

typedef unsigned long long ull;

// Problem dims
#define S_   4096
#define T_   64
#define I_   64
#define EH_  128
#define E_   256
#define H_   512
#define O_   128
#define F1_  256
#define F2_  64
#define G4H_ (4*H_)       // 2048
#define KG_  (E_+H_)      // 768
#define NK16W (KG_/16)    // 48
#define NN16 (G4H_/16)    // 128
#define ST_  (S_*T_)      // 262144

// ---------------- device scratch ----------------
__device__ float g_laneC;
__device__ __half g_x1h[(size_t)ST_ * EH_];      // x1 fp16 hi
__device__ __half g_x1l[(size_t)ST_ * EH_];      // x1 fp16 lo
__device__ __half g_xemb[(size_t)ST_ * E_];      // [T][S][E] fp16 (single)
__device__ uint4 g_Bfrag[(size_t)NK16W * NN16 * 32];   // 3.1 MB gates W fragments
__device__ uint4 g_W2frag[(size_t)16 * 16 * 32];       // 128 KB We2 fragments (hi 0-7, lo 8-15)
__device__ float g_bcomb[G4H_];
__device__ float g_h[(size_t)S_ * H_];
__device__ __half g_hh[(size_t)S_ * H_];         // pooled h fp16 (single)
__device__ float g_hraw[(size_t)S_ * H_];
__device__ float g_c[(size_t)S_ * H_];
__device__ float g_o1[(size_t)S_ * O_];
__device__ float g_o2[(size_t)S_ * F1_];
__device__ float g_o3[(size_t)S_ * F2_];

// ---------------- helpers ----------------
__device__ __forceinline__ uint32_t smem_u32(const void* p) {
    uint32_t a;
    asm("{ .reg .u64 t; cvta.to.shared.u64 t, %1; cvt.u32.u64 %0, t; }" : "=r"(a) : "l"(p));
    return a;
}
#define CP16(dst, src) asm volatile("cp.async.cg.shared.global [%0], [%1], 16;" :: "r"(dst), "l"(src))
#define CP_COMMIT()    asm volatile("cp.async.commit_group;" ::: "memory")
#define CP_WAIT1()     asm volatile("cp.async.wait_group 1;" ::: "memory")
#define CP_WAIT0()     asm volatile("cp.async.wait_group 0;" ::: "memory")

#define MMA16816(c, a, b) \
    asm volatile("mma.sync.aligned.m16n8k16.row.col.f32.f16.f16.f32 " \
        "{%0,%1,%2,%3}, {%4,%5,%6,%7}, {%8,%9}, {%0,%1,%2,%3};" \
        : "+f"((c)[0]), "+f"((c)[1]), "+f"((c)[2]), "+f"((c)[3]) \
        : "r"((a)[0]), "r"((a)[1]), "r"((a)[2]), "r"((a)[3]), \
          "r"((b)[0]), "r"((b)[1]))

#define LDSM4(r0, r1, r2, r3, addr) \
    asm volatile("ldmatrix.sync.aligned.m8n8.x4.shared.b16 {%0,%1,%2,%3}, [%4];" \
        : "=r"(r0), "=r"(r1), "=r"(r2), "=r"(r3) : "r"(addr))

#define FMA2(d, a, b) asm("fma.rn.f32x2 %0, %1, %2, %0;" : "+l"(d) : "l"(a), "l"(b))
#define PACK2(d, x)   asm("mov.b64 %0, {%1, %1};" : "=l"(d) : "f"(x))
__device__ __forceinline__ float2 unpk(ull v) {
    float2 r;
    asm("mov.b64 {%0, %1}, %2;" : "=f"(r.x), "=f"(r.y) : "l"(v));
    return r;
}
__device__ __forceinline__ float sigf(float x) { return __fdividef(1.0f, 1.0f + __expf(-x)); }
__device__ __forceinline__ float tanhf_(float x) {
    return 2.0f * __fdividef(1.0f, 1.0f + __expf(-2.0f * x)) - 1.0f;
}
__device__ __forceinline__ uint32_t pack_h2(__half a, __half b) {
    uint16_t ua = *reinterpret_cast<uint16_t*>(&a);
    uint16_t ub = *reinterpret_cast<uint16_t*>(&b);
    return (uint32_t)ua | ((uint32_t)ub << 16);
}

// ---------------- prep: gates W fragments + We2 fragments + bias + lane gate ----------------
__global__ void prep_all(const float* __restrict__ Wih, const float* __restrict__ Whh,
                         const float* __restrict__ bih, const float* __restrict__ bhh,
                         const float* __restrict__ We2,
                         const float* __restrict__ lane,
                         const float* __restrict__ Wlg1, const float* __restrict__ blg1,
                         const float* __restrict__ Wlg2, const float* __restrict__ blg2) {
    int k16 = blockIdx.x;   // 0..47
    int n16 = blockIdx.y;   // 0..127
    int ln = threadIdx.x;   // 0..31

    // gates weights (fp16 single) over K=768
    {
        uint32_t vals[4];
#pragma unroll
        for (int j = 0; j < 4; j++) {
            int n = n16 * 16 + ((j >> 1) * 8) + (ln >> 2);
            int kp = k16 * 16 + ((j & 1) * 8) + (ln & 3) * 2;
            int orig = (n & 3) * H_ + (n >> 2);
            float w0 = (kp < E_) ? Wih[(size_t)orig * E_ + kp] : Whh[(size_t)orig * H_ + (kp - E_)];
            int kp1 = kp + 1;
            float w1 = (kp1 < E_) ? Wih[(size_t)orig * E_ + kp1] : Whh[(size_t)orig * H_ + (kp1 - E_)];
            vals[j] = pack_h2(__float2half(w0), __float2half(w1));
        }
        g_Bfrag[((size_t)k16 * NN16 + n16) * 32 + ln] =
            make_uint4(vals[0], vals[1], vals[2], vals[3]);
    }

    // We2 fragments: k16 slots 0-7 = hi, 8-15 = lo  (We2 is [E,EH] = [256,128])
    if (k16 < 16 && n16 < 16) {
        uint32_t vals[4];
#pragma unroll
        for (int j = 0; j < 4; j++) {
            int n = n16 * 16 + ((j >> 1) * 8) + (ln >> 2);
            int kp = (k16 & 7) * 16 + ((j & 1) * 8) + (ln & 3) * 2;
            float w0 = We2[(size_t)n * EH_ + kp];
            float w1 = We2[(size_t)n * EH_ + kp + 1];
            __half h0, h1;
            if (k16 < 8) { h0 = __float2half(w0); h1 = __float2half(w1); }
            else {
                __half a = __float2half(w0), b = __float2half(w1);
                h0 = __float2half(w0 - __half2float(a));
                h1 = __float2half(w1 - __half2float(b));
            }
            vals[j] = pack_h2(h0, h1);
        }
        g_W2frag[((size_t)k16 * 16 + n16) * 32 + ln] =
            make_uint4(vals[0], vals[1], vals[2], vals[3]);
    }

    if (k16 == 0 && ln < 16) {
        int r = n16 * 16 + ln;
        int orig = (r & 3) * H_ + (r >> 2);
        g_bcomb[r] = bih[orig] + bhh[orig];
    }
    if (k16 == 0 && n16 == 0) {
        float lg = fmaxf(lane[0] * Wlg1[ln] + blg1[ln], 0.0f);
        float p = lg * Wlg2[ln];
#pragma unroll
        for (int o = 16; o > 0; o >>= 1) p += __shfl_down_sync(0xFFFFFFFFu, p, o);
        if (ln == 0) g_laneC = 1.0f / (1.0f + expf(-(p + blg2[0])));
    }
}

// ---------------- scalar FFMA2 SGEMM (embedding GEMM1 + head) ----------------
#define BM 128
#define BN 128
#define BK 8
#define FL_RELU    1
#define FL_SCALEA  2
#define FL_SPLIT1  8   // write fp16 hi/lo to g_x1h/g_x1l (row-major)

__global__ __launch_bounds__(256, 2)
void sgemm2(int M, int N, int K,
            const float* __restrict__ A, int lda,
            const float* __restrict__ B,
            const float* __restrict__ bias,
            float* __restrict__ C, int ldc, int flags)
{
    __shared__ __align__(16) float As[BK][BM];
    __shared__ __align__(16) float Bs[BK][BN];

    const int tid = threadIdx.x;
    const int tx = tid & 15;
    const int ty = tid >> 4;
    const int bm = blockIdx.y * BM;
    const int bn = blockIdx.x * BN;
    const float scale = (flags & FL_SCALEA) ? g_laneC : 1.0f;
    const int lRow = tid >> 1;
    const int lCol = (tid & 1) * 4;

    ull acc[8][4];
#pragma unroll
    for (int i = 0; i < 8; i++)
#pragma unroll
        for (int p = 0; p < 4; p++) acc[i][p] = 0ull;

    for (int k0 = 0; k0 < K; k0 += BK) {
        float4 av = make_float4(0.f, 0.f, 0.f, 0.f);
        int ar = bm + lRow;
        if (ar < M) av = *reinterpret_cast<const float4*>(A + (size_t)ar * lda + (k0 + lCol));
        As[lCol + 0][lRow] = av.x * scale;
        As[lCol + 1][lRow] = av.y * scale;
        As[lCol + 2][lRow] = av.z * scale;
        As[lCol + 3][lRow] = av.w * scale;

        float4 bv = make_float4(0.f, 0.f, 0.f, 0.f);
        int br = bn + lRow;
        if (br < N) bv = *reinterpret_cast<const float4*>(B + (size_t)br * K + (k0 + lCol));
        Bs[lCol + 0][lRow] = bv.x;
        Bs[lCol + 1][lRow] = bv.y;
        Bs[lCol + 2][lRow] = bv.z;
        Bs[lCol + 3][lRow] = bv.w;

        __syncthreads();
#pragma unroll
        for (int k = 0; k < BK; k++) {
            float4 a0 = *reinterpret_cast<const float4*>(&As[k][ty * 4]);
            float4 a1 = *reinterpret_cast<const float4*>(&As[k][64 + ty * 4]);
            const ull* bp0 = reinterpret_cast<const ull*>(&Bs[k][tx * 4]);
            const ull* bp1 = reinterpret_cast<const ull*>(&Bs[k][64 + tx * 4]);
            ull b0 = bp0[0], b1 = bp0[1], b2 = bp1[0], b3 = bp1[1];
            float as[8] = {a0.x, a0.y, a0.z, a0.w, a1.x, a1.y, a1.z, a1.w};
            ull aa;
#pragma unroll
            for (int i = 0; i < 8; i++) {
                PACK2(aa, as[i]);
                FMA2(acc[i][0], aa, b0);
                FMA2(acc[i][1], aa, b1);
                FMA2(acc[i][2], aa, b2);
                FMA2(acc[i][3], aa, b3);
            }
        }
        __syncthreads();
    }

#pragma unroll
    for (int i = 0; i < 8; i++) {
        int row = bm + ((i < 4) ? (ty * 4 + i) : (64 + ty * 4 + (i - 4)));
        if (row >= M) continue;
#pragma unroll
        for (int p = 0; p < 4; p++) {
            float2 v = unpk(acc[i][p]);
            int c0 = bn + ((p < 2) ? (tx * 4 + p * 2) : (64 + tx * 4 + (p - 2) * 2));
#pragma unroll
            for (int q = 0; q < 2; q++) {
                int col = c0 + q;
                if (col >= N) continue;
                float val = (q == 0) ? v.x : v.y;
                if (bias) val += bias[col];
                if (flags & FL_RELU) val = fmaxf(val, 0.0f);
                if (flags & FL_SPLIT1) {
                    __half hi = __float2half(val);
                    g_x1h[(size_t)row * EH_ + col] = hi;
                    g_x1l[(size_t)row * EH_ + col] = __float2half(val - __half2float(hi));
                } else {
                    C[(size_t)row * ldc + col] = val;
                }
            }
        }
    }
}

// ---------------- shared mma-mainloop constants ----------------
#define GBK 128
#define AROW 272                   // 256 B row + 16 pad
#define A_BYTES (128 * AROW)       // 34816 per stage
#define SM_TOT  (2 * A_BYTES)      // 69632

// ============ embedding GEMM2 on tensor cores: xemb = relu(x1 @ We2^T + be2) ============
// 3-term fp16 split over K'=384; epilogue stores SINGLE fp16 xemb, [T][S][E] permuted.
__global__ __launch_bounds__(256, 2)
void emb_mma(const float* __restrict__ be2)
{
    extern __shared__ char smem[];
    const uint32_t sb = smem_u32(smem);
    const int tid = threadIdx.x;
    const int lane = tid & 31;
    const int wid = tid >> 5;
    const int wm = wid & 3;
    const int wn = wid >> 2;
    const int bm = blockIdx.y * 128;
    const int bn = blockIdx.x * 128;
    const int n16b = blockIdx.x * 8 + wn * 4;

    float acc[2][8][4];
#pragma unroll
    for (int mf = 0; mf < 2; mf++)
#pragma unroll
        for (int nf = 0; nf < 8; nf++)
#pragma unroll
            for (int r = 0; r < 4; r++) acc[mf][nf][r] = 0.0f;

    auto load_chunk = [&](int ck, int st) {
        const __half* asrc = ((ck == 1) ? g_x1l : g_x1h) + (size_t)bm * EH_;
        const uint32_t abase = sb + (uint32_t)(st * A_BYTES);
#pragma unroll
        for (int it = 0; it < 8; it++) {
            int i = tid + it * 256;
            int row = i >> 4, sg = i & 15;
            CP16(abase + row * AROW + sg * 16, asrc + (size_t)row * EH_ + sg * 8);
        }
    };

    const int grp = lane >> 3, lr = lane & 7;
    const int a_row = wm * 32 + (grp & 1) * 8 + lr;
    const int a_kh  = (grp >> 1) * 8;
    const uint4* __restrict__ bfp = g_W2frag + lane;

    load_chunk(0, 0);
    CP_COMMIT();

    const int k16bases[3] = {0, 0, 8};
#pragma unroll
    for (int ck = 0; ck < 3; ck++) {
        const int st = ck & 1;
        if (ck + 1 < 3) {
            load_chunk(ck + 1, st ^ 1);
            CP_COMMIT();
            CP_WAIT1();
        } else {
            CP_WAIT0();
        }
        __syncthreads();

        const uint32_t abase = sb + (uint32_t)(st * A_BYTES);
        const int k16base = k16bases[ck];

        uint4 bv[4];
#pragma unroll
        for (int q = 0; q < 4; q++)
            bv[q] = __ldg(bfp + ((size_t)k16base * 16 + (n16b + q)) * 32);

#pragma unroll
        for (int kh = 0; kh < 8; kh++) {
            uint4 bnx[4];
            if (kh < 7) {
#pragma unroll
                for (int q = 0; q < 4; q++)
                    bnx[q] = __ldg(bfp + ((size_t)(k16base + kh + 1) * 16 + (n16b + q)) * 32);
            }
            const int k0 = kh * 16;
            uint32_t af[2][4];
#pragma unroll
            for (int mf = 0; mf < 2; mf++)
                LDSM4(af[mf][0], af[mf][1], af[mf][2], af[mf][3],
                      abase + (uint32_t)((a_row + mf * 16) * AROW + (k0 + a_kh) * 2));
            uint32_t bf[8][2];
#pragma unroll
            for (int q = 0; q < 4; q++) {
                bf[2 * q][0] = bv[q].x;
                bf[2 * q][1] = bv[q].y;
                bf[2 * q + 1][0] = bv[q].z;
                bf[2 * q + 1][1] = bv[q].w;
            }
#pragma unroll
            for (int mf = 0; mf < 2; mf++)
#pragma unroll
                for (int nf = 0; nf < 8; nf++)
                    MMA16816(acc[mf][nf], af[mf], bf[nf]);
#pragma unroll
            for (int q = 0; q < 4; q++) bv[q] = bnx[q];
        }
        __syncthreads();
    }

    // ---- epilogue: bias + relu + single-fp16 [T][S][E] permuted store ----
    const int qg = lane & 3;
#pragma unroll
    for (int mf = 0; mf < 2; mf++) {
        const int r0 = bm + wm * 32 + mf * 16 + (lane >> 2);
        const size_t orow0 = ((size_t)(r0 & (T_ - 1)) * S_ + (r0 >> 6));
        const size_t orow1 = ((size_t)((r0 + 8) & (T_ - 1)) * S_ + ((r0 + 8) >> 6));
#pragma unroll
        for (int nf = 0; nf < 8; nf++) {
            const int c = bn + wn * 64 + nf * 8 + qg * 2;
            float2 bb = *reinterpret_cast<const float2*>(&be2[c]);
#pragma unroll
            for (int h = 0; h < 2; h++) {
                float v0 = fmaxf(acc[mf][nf][h * 2 + 0] + bb.x, 0.0f);
                float v1 = fmaxf(acc[mf][nf][h * 2 + 1] + bb.y, 0.0f);
                size_t orow = h ? orow1 : orow0;
                *reinterpret_cast<uint32_t*>(&g_xemb[orow * E_ + c]) =
                    pack_h2(__float2half(v0), __float2half(v1));
            }
        }
    }
}

// ============ gates GEMM: single fp16 x single fp16, K=768 (6 chunks of 128) ============
__global__ __launch_bounds__(256, 2)
void gates_mma(int t)
{
    extern __shared__ char smem[];
    const uint32_t sb = smem_u32(smem);
    const int tid = threadIdx.x;
    const int lane = tid & 31;
    const int wid = tid >> 5;
    const int wm = wid & 3;
    const int wn = wid >> 2;
    const int bm = blockIdx.y * 128;
    const int bn = blockIdx.x * 128;
    const int n16b = blockIdx.x * 8 + wn * 4;

    const int nch = (t == 0) ? 2 : 6;   // t=0: h==0, only x chunks (kk<256)

    float acc[2][8][4];
#pragma unroll
    for (int mf = 0; mf < 2; mf++)
#pragma unroll
        for (int nf = 0; nf < 8; nf++)
#pragma unroll
            for (int r = 0; r < 4; r++) acc[mf][nf][r] = 0.0f;

    auto load_chunk = [&](int ck, int st) {
        const int kk = ck * GBK;        // 0..640
        const __half* asrc;
        size_t astr;
        if (kk < E_) {
            asrc = g_xemb + ((size_t)t * S_ + bm) * E_ + kk;
            astr = E_;
        } else {
            asrc = g_hh + (size_t)bm * H_ + (kk - E_);
            astr = H_;
        }
        const uint32_t abase = sb + (uint32_t)(st * A_BYTES);
#pragma unroll
        for (int it = 0; it < 8; it++) {
            int i = tid + it * 256;
            int row = i >> 4, sg = i & 15;
            CP16(abase + row * AROW + sg * 16, asrc + (size_t)row * astr + sg * 8);
        }
    };

    const int grp = lane >> 3, lr = lane & 7;
    const int a_row = wm * 32 + (grp & 1) * 8 + lr;
    const int a_kh  = (grp >> 1) * 8;
    const uint4* __restrict__ bfp = g_Bfrag + lane;

    load_chunk(0, 0);
    CP_COMMIT();

    for (int ck = 0; ck < nch; ck++) {
        const int st = ck & 1;
        if (ck + 1 < nch) {
            load_chunk(ck + 1, st ^ 1);
            CP_COMMIT();
            CP_WAIT1();
        } else {
            CP_WAIT0();
        }
        __syncthreads();

        const uint32_t abase = sb + (uint32_t)(st * A_BYTES);
        const int k16base = ck * 8;

        uint4 bv[4];
#pragma unroll
        for (int q = 0; q < 4; q++)
            bv[q] = __ldg(bfp + ((size_t)k16base * NN16 + (n16b + q)) * 32);

#pragma unroll
        for (int kh = 0; kh < 8; kh++) {
            uint4 bnx[4];
            if (kh < 7) {
#pragma unroll
                for (int q = 0; q < 4; q++)
                    bnx[q] = __ldg(bfp + ((size_t)(k16base + kh + 1) * NN16 + (n16b + q)) * 32);
            }
            const int k0 = kh * 16;
            uint32_t af[2][4];
#pragma unroll
            for (int mf = 0; mf < 2; mf++)
                LDSM4(af[mf][0], af[mf][1], af[mf][2], af[mf][3],
                      abase + (uint32_t)((a_row + mf * 16) * AROW + (k0 + a_kh) * 2));
            uint32_t bf[8][2];
#pragma unroll
            for (int q = 0; q < 4; q++) {
                bf[2 * q][0] = bv[q].x;
                bf[2 * q][1] = bv[q].y;
                bf[2 * q + 1][0] = bv[q].z;
                bf[2 * q + 1][1] = bv[q].w;
            }
#pragma unroll
            for (int mf = 0; mf < 2; mf++)
#pragma unroll
                for (int nf = 0; nf < 8; nf++)
                    MMA16816(acc[mf][nf], af[mf], bf[nf]);
#pragma unroll
            for (int q = 0; q < 4; q++) bv[q] = bnx[q];
        }
        __syncthreads();
    }

    // ---- register epilogue: shfl pairs (i,f)<->(g,o), fused LSTM cell ----
    const int qg = lane & 3;
    const bool evenT = (qg & 1) == 0;
    const int unit_base = (bn + wn * 64) >> 2;
#pragma unroll
    for (int mf = 0; mf < 2; mf++) {
        const int rloc = wm * 32 + mf * 16 + (lane >> 2);
#pragma unroll
        for (int nf = 0; nf < 8; nf++) {
            const int col0 = bn + wn * 64 + nf * 8 + qg * 2;
            float2 bb = *reinterpret_cast<const float2*>(&g_bcomb[col0]);
            float c0 = acc[mf][nf][0] + bb.x;
            float c1 = acc[mf][nf][1] + bb.y;
            float c2 = acc[mf][nf][2] + bb.x;
            float c3 = acc[mf][nf][3] + bb.y;
            float x0 = __shfl_xor_sync(0xFFFFFFFFu, c0, 1);
            float x1 = __shfl_xor_sync(0xFFFFFFFFu, c1, 1);
            float x2 = __shfl_xor_sync(0xFFFFFFFFu, c2, 1);
            float x3 = __shfl_xor_sync(0xFFFFFFFFu, c3, 1);
            float iv, fv, gv, ov; int rr;
            if (evenT) { iv = c0; fv = c1; gv = x0; ov = x1; rr = rloc; }
            else       { iv = x2; fv = x3; gv = c2; ov = c3; rr = rloc + 8; }
            const int unit = unit_base + nf * 2 + (qg >> 1);
            size_t cidx = (size_t)(bm + rr) * H_ + unit;
            float cold = (t == 0) ? 0.0f : g_c[cidx];
            float cn = sigf(fv) * cold + sigf(iv) * tanhf_(gv);
            g_c[cidx] = cn;
            g_hraw[cidx] = sigf(ov) * tanhf_(cn);
        }
    }
}

// ---------------- spatial maxpool + single-fp16 h ----------------
__global__ void maxpool_kernel(int writeH) {
    int idx = blockIdx.x * blockDim.x + threadIdx.x;
    if (idx >= S_ * H_) return;
    int s = idx >> 9;
    float v = g_hraw[idx];
    if (s > 0)       v = fmaxf(v, g_hraw[idx - H_]);
    if (s < S_ - 1)  v = fmaxf(v, g_hraw[idx + H_]);
    if (writeH) g_h[idx] = v;
    g_hh[idx] = __float2half(v);
}

// ---------------- final head ----------------
__global__ void head_final_kernel(const float* __restrict__ Wf3,
                                  const float* __restrict__ bf3,
                                  float* __restrict__ out) {
    __shared__ float red[F2_];
    int s = blockIdx.x;
    int t = threadIdx.x;
    red[t] = g_o3[(size_t)s * F2_ + t] * Wf3[t];
    __syncthreads();
#pragma unroll
    for (int o = 32; o > 0; o >>= 1) {
        if (t < o) red[t] += red[t + o];
        __syncthreads();
    }
    if (t == 0) out[s] = (red[0] + bf3[0]) / g_laneC;
}

__global__ void finalize_kernel(float* __restrict__ out) {
    int idx = blockIdx.x * blockDim.x + threadIdx.x;
    if (idx >= S_ * H_) return;
    out[S_ + idx] = g_h[idx];
    out[S_ + (size_t)S_ * H_ + idx] = g_c[idx];
}

// ---------------- host launcher ----------------
extern "C" void kernel_launch(void* const* d_in, const int* in_sizes, int n_in,
                              void* d_out, int out_size) {
    const float* inputData = (const float*)d_in[0];
    const float* lane      = (const float*)d_in[1];
    const float* Wlg1      = (const float*)d_in[2];
    const float* blg1      = (const float*)d_in[3];
    const float* Wlg2      = (const float*)d_in[4];
    const float* blg2      = (const float*)d_in[5];
    const float* We1       = (const float*)d_in[6];
    const float* be1       = (const float*)d_in[7];
    const float* We2       = (const float*)d_in[8];
    const float* be2       = (const float*)d_in[9];
    const float* Wih       = (const float*)d_in[10];
    const float* bih       = (const float*)d_in[11];
    const float* Whh       = (const float*)d_in[12];
    const float* bhh       = (const float*)d_in[13];
    const float* Wout      = (const float*)d_in[14];
    const float* bout      = (const float*)d_in[15];
    const float* Wf1       = (const float*)d_in[16];
    const float* bf1       = (const float*)d_in[17];
    const float* Wf2       = (const float*)d_in[18];
    const float* bf2       = (const float*)d_in[19];
    const float* Wf3       = (const float*)d_in[20];
    const float* bf3       = (const float*)d_in[21];
    float* out = (float*)d_out;

    float *p_h, *p_o1, *p_o2, *p_o3;
    cudaGetSymbolAddress((void**)&p_h,  g_h);
    cudaGetSymbolAddress((void**)&p_o1, g_o1);
    cudaGetSymbolAddress((void**)&p_o2, g_o2);
    cudaGetSymbolAddress((void**)&p_o3, g_o3);

    static int smem_set = 0;
    if (!smem_set) {
        cudaFuncSetAttribute(gates_mma, cudaFuncAttributeMaxDynamicSharedMemorySize, SM_TOT);
        cudaFuncSetAttribute(emb_mma, cudaFuncAttributeMaxDynamicSharedMemorySize, SM_TOT);
        smem_set = 1;
    }

    dim3 blk(256);

    // #1: prep
    prep_all<<<dim3(NK16W, NN16), 32>>>(Wih, Whh, bih, bhh, We2,
                                        lane, Wlg1, blg1, Wlg2, blg2);
    // #2: embedding GEMM1 (scalar; writes x1 fp16 hi/lo)
    sgemm2<<<dim3(EH_ / BN, ST_ / BM), blk>>>(ST_, EH_, I_, inputData, I_, We1, be1,
                                              nullptr, EH_, FL_RELU | FL_SCALEA | FL_SPLIT1);
    // #3: embedding GEMM2 (tensor cores; writes single-fp16 xemb permuted)
    emb_mma<<<dim3(E_ / 128, ST_ / 128), blk, SM_TOT>>>(be2);

    // #4 onward: recurrence (gates t=0 is the profiled launch)
    int ew = S_ * H_;
    dim3 ggrid(G4H_ / 128, S_ / 128);  // 16 x 32 = 512 CTAs
    for (int t = 0; t < T_; t++) {
        gates_mma<<<ggrid, 256, SM_TOT>>>(t);
        maxpool_kernel<<<(ew + 255) / 256, 256>>>(t == T_ - 1 ? 1 : 0);
    }

    // output head (scalar GEMMs; small)
    sgemm2<<<dim3(O_ / BN, S_ / BM), blk>>>(S_, O_, H_, p_h, H_, Wout, bout,
                                            p_o1, O_, 0);
    sgemm2<<<dim3((F1_ + BN - 1) / BN, S_ / BM), blk>>>(S_, F1_, O_, p_o1, O_, Wf1, bf1,
                                                        p_o2, F1_, FL_RELU);
    sgemm2<<<dim3((F2_ + BN - 1) / BN, S_ / BM), blk>>>(S_, F2_, F1_, p_o2, F1_, Wf2, bf2,
                                                        p_o3, F2_, FL_RELU);
    head_final_kernel<<<S_, F2_>>>(Wf3, bf3, out);
    finalize_kernel<<<(ew + 255) / 256, 256>>>(out);
}